// round 1
// baseline (speedup 1.0000x reference)
#include <cuda_runtime.h>

// VectorQuantizer: N=16384 tokens (16 x 32 x 32), D=256, K=8192 codes.
// Outputs (float32, concatenated): quantized [16,256,32,32] (4194304),
// indices [16,1024] (16384), vq_loss (1).

#define NTOK   16384
#define KCB    8192
#define DIM    256
#define TM     64
#define TN     64
#define KD     32
#define NQELEM (NTOK * DIM)   // 4194304

__device__ float  g_sf[NTOK];            // per-token ||f||^2 (fp32, sequential sum)
__device__ float  g_se[KCB];             // per-code  ||e||^2
__device__ int    g_bestidx[NTOK];       // argmin result
__device__ double g_partial[NTOK / 64];  // per-block loss partials

// ---------------------------------------------------------------------------
// sf[t] = sum_c x[b,c,hw]^2, sequential over c in fp32 (mirrors a simple
// fp32 reduction; this value anchors the distance rounding grid).
// One thread per token; warp lanes hit consecutive hw -> fully coalesced.
// ---------------------------------------------------------------------------
__global__ void sf_kernel(const float* __restrict__ x) {
    int t = blockIdx.x * blockDim.x + threadIdx.x;
    int b = t >> 10, hw = t & 1023;
    const float* p = x + ((size_t)b << 18) + hw;
    float s = 0.f;
    #pragma unroll 16
    for (int c = 0; c < DIM; c++) {
        float v = p[(size_t)c << 10];
        s = s + v * v;
    }
    g_sf[t] = s;
}

// ---------------------------------------------------------------------------
// se[k] = sum_d cb[k,d]^2. One warp per codebook row.
// (se ~ 1.3e-6 is far below the distance ulp, so its rounding never matters.)
// ---------------------------------------------------------------------------
__global__ void se_kernel(const float* __restrict__ cb) {
    int k    = blockIdx.x * 8 + (threadIdx.x >> 5);
    int lane = threadIdx.x & 31;
    const float4* row = (const float4*)(cb + (size_t)k * DIM);
    float s = 0.f;
    #pragma unroll
    for (int j = 0; j < 2; j++) {
        float4 v = row[lane + 32 * j];
        s += v.x * v.x + v.y * v.y + v.z * v.z + v.w * v.w;
    }
    #pragma unroll
    for (int o = 16; o; o >>= 1) s += __shfl_xor_sync(0xffffffffu, s, o);
    if (lane == 0) g_se[k] = s;
}

// ---------------------------------------------------------------------------
// Fused distance-GEMM + argmin.
// Block: 256 threads (16x16), tile TM=64 tokens x TN=64 codes, full D=256 per
// code tile. A (tokens) resident in smem for the whole block (64 KB); B
// (codebook) double-buffered in 32x64 stages. Each thread owns a 4x4 register
// tile; dot products accumulate sequentially over d=0..255 in fp32.
// dist = (sf - 2*g) + se  (exact fp32 rounding structure of the reference),
// argmin with first-index tie-break.
// ---------------------------------------------------------------------------
__global__ void __launch_bounds__(256) vq_argmin_kernel(const float* __restrict__ x,
                                                        const float* __restrict__ cb) {
    extern __shared__ float smem[];
    float* As = smem;               // [DIM][TM]
    float* Bs = smem + DIM * TM;    // [2][KD][TN]

    const int tid = threadIdx.x;
    const int tx = tid & 15, ty = tid >> 4;
    const int m0 = blockIdx.x * TM;

    // Load A tile: 64 tokens share one batch b (64 | 1024), hw contiguous.
    {
        const int b   = m0 >> 10;
        const int hw0 = m0 & 1023;
        const float* base = x + ((size_t)b << 18) + hw0;
        for (int l = tid; l < DIM * TM; l += 256) {
            int c = l >> 6, i = l & 63;
            As[c * TM + i] = base[((size_t)c << 10) + i];
        }
    }

    float sfm[4];
    #pragma unroll
    for (int r = 0; r < 4; r++) sfm[r] = g_sf[m0 + ty * 4 + r];

    float bestd[4];
    int   besti[4];
    #pragma unroll
    for (int r = 0; r < 4; r++) { bestd[r] = 3.402823466e38f; besti[r] = 0; }

    const int kk = tid & 63;   // k-row within tile this thread loads
    const int j0 = tid >> 6;   // float4 slot 0..3 (covers j0 and j0+4)

    __syncthreads();

    for (int k0 = 0; k0 < KCB; k0 += TN) {
        float acc[4][4];
        #pragma unroll
        for (int r = 0; r < 4; r++)
            #pragma unroll
            for (int c = 0; c < 4; c++) acc[r][c] = 0.f;

        const float4* crow = (const float4*)(cb + (size_t)(k0 + kk) * DIM);

        // Stage 0 load (exposed; ~300 cyc vs ~8K cyc compute per tile)
        {
            float4 v0 = crow[j0];
            float4 v1 = crow[j0 + 4];
            float* B = Bs;
            B[(4 * j0 + 0) * TN + kk] = v0.x;
            B[(4 * j0 + 1) * TN + kk] = v0.y;
            B[(4 * j0 + 2) * TN + kk] = v0.z;
            B[(4 * j0 + 3) * TN + kk] = v0.w;
            B[(4 * (j0 + 4) + 0) * TN + kk] = v1.x;
            B[(4 * (j0 + 4) + 1) * TN + kk] = v1.y;
            B[(4 * (j0 + 4) + 2) * TN + kk] = v1.z;
            B[(4 * (j0 + 4) + 3) * TN + kk] = v1.w;
        }
        __syncthreads();

        #pragma unroll
        for (int s = 0; s < 8; s++) {
            float4 n0, n1;
            if (s < 7) {                       // prefetch next stage into regs
                n0 = crow[8 * (s + 1) + j0];
                n1 = crow[8 * (s + 1) + j0 + 4];
            }
            const float* B = Bs + (s & 1) * (KD * TN);
            #pragma unroll
            for (int d = 0; d < KD; d++) {
                float4 a4 = *(const float4*)&As[(s * KD + d) * TM + ty * 4];
                float4 b4 = *(const float4*)&B[d * TN + tx * 4];
                float a[4] = {a4.x, a4.y, a4.z, a4.w};
                float b[4] = {b4.x, b4.y, b4.z, b4.w};
                #pragma unroll
                for (int r = 0; r < 4; r++)
                    #pragma unroll
                    for (int c = 0; c < 4; c++)
                        acc[r][c] += a[r] * b[c];
            }
            __syncthreads();
            if (s < 7) {
                float* Bn = Bs + ((s + 1) & 1) * (KD * TN);
                Bn[(4 * j0 + 0) * TN + kk] = n0.x;
                Bn[(4 * j0 + 1) * TN + kk] = n0.y;
                Bn[(4 * j0 + 2) * TN + kk] = n0.z;
                Bn[(4 * j0 + 3) * TN + kk] = n0.w;
                Bn[(4 * (j0 + 4) + 0) * TN + kk] = n1.x;
                Bn[(4 * (j0 + 4) + 1) * TN + kk] = n1.y;
                Bn[(4 * (j0 + 4) + 2) * TN + kk] = n1.z;
                Bn[(4 * (j0 + 4) + 3) * TN + kk] = n1.w;
                __syncthreads();
            }
        }

        // Distance + running argmin (k ascending -> strict < keeps first idx)
        const float4 se4 = *(const float4*)(g_se + k0 + tx * 4);
        const float se_[4] = {se4.x, se4.y, se4.z, se4.w};
        #pragma unroll
        for (int r = 0; r < 4; r++) {
            #pragma unroll
            for (int c = 0; c < 4; c++) {
                float dist = (sfm[r] - 2.0f * acc[r][c]) + se_[c];
                int ki = k0 + tx * 4 + c;
                if (dist < bestd[r]) { bestd[r] = dist; besti[r] = ki; }
            }
        }
    }

    // Cross-thread reduce over the 16 tx columns per token row.
    __syncthreads();
    float* rd = smem;                   // [TM][16]
    int*   ri = (int*)(smem + TM * 16); // [TM][16]
    #pragma unroll
    for (int r = 0; r < 4; r++) {
        rd[(ty * 4 + r) * 16 + tx] = bestd[r];
        ri[(ty * 4 + r) * 16 + tx] = besti[r];
    }
    __syncthreads();
    if (tid < TM) {
        float bd = rd[tid * 16];
        int   bi = ri[tid * 16];
        #pragma unroll
        for (int t = 1; t < 16; t++) {
            float d2 = rd[tid * 16 + t];
            int   i2 = ri[tid * 16 + t];
            if (d2 < bd || (d2 == bd && i2 < bi)) { bd = d2; bi = i2; }
        }
        g_bestidx[m0 + tid] = bi;
    }
}

// ---------------------------------------------------------------------------
// Gather + straight-through output + indices + loss partials.
// quantized_out = x + (q - x), replicating the reference's double rounding.
// Loss accumulated per-thread in double with a fixed-order tree reduce
// (deterministic across replays).
// ---------------------------------------------------------------------------
__global__ void __launch_bounds__(256) vq_output_kernel(const float* __restrict__ x,
                                                        const float* __restrict__ cb,
                                                        float* __restrict__ out,
                                                        float* __restrict__ idx_out) {
    __shared__ double sred[256];
    const int tid = threadIdx.x;
    const int m0  = blockIdx.x * 64;
    const int t   = m0 + (tid & 63);
    const int cg  = tid >> 6;
    const int b = t >> 10, hw = t & 1023;
    const int idx = g_bestidx[t];
    const float* xp  = x  + ((size_t)b << 18) + hw;
    const float* cbp = cb + (size_t)idx * DIM;
    float* op = out + ((size_t)b << 18) + hw;
    double ls = 0.0;
    for (int c = cg * 64; c < cg * 64 + 64; c++) {
        float xv = xp[(size_t)c << 10];
        float q  = cbp[c];
        float d  = q - xv;
        op[(size_t)c << 10] = xv + d;
        ls += (double)(d * d);
    }
    if (cg == 0) idx_out[t] = (float)idx;
    sred[tid] = ls;
    __syncthreads();
    for (int o = 128; o; o >>= 1) {
        if (tid < o) sred[tid] += sred[tid + o];
        __syncthreads();
    }
    if (tid == 0) g_partial[blockIdx.x] = sred[0];
}

__global__ void vq_loss_kernel(float* __restrict__ loss_out) {
    double s = 0.0;
    for (int i = 0; i < NTOK / 64; i++) s += g_partial[i];
    float m = (float)(s / (double)NQELEM);       // e_loss == q_loss numerically
    loss_out[0] = m + 0.25f * m;                 // fl(m + fl(0.25*m))
}

// ---------------------------------------------------------------------------
extern "C" void kernel_launch(void* const* d_in, const int* in_sizes, int n_in,
                              void* d_out, int out_size) {
    const float* x  = (const float*)d_in[0];
    const float* cb = (const float*)d_in[1];
    if (n_in >= 2 && in_sizes[0] == KCB * DIM && in_sizes[1] == NQELEM) {
        const float* tmp = x; x = cb; cb = tmp;   // defensive: swapped order
    }
    float* out = (float*)d_out;

    sf_kernel<<<NTOK / 256, 256>>>(x);
    se_kernel<<<KCB / 8, 256>>>(cb);

    const size_t smem_bytes = (size_t)(DIM * TM + 2 * KD * TN) * sizeof(float); // 81920
    cudaFuncSetAttribute(vq_argmin_kernel,
                         cudaFuncAttributeMaxDynamicSharedMemorySize,
                         (int)smem_bytes);
    vq_argmin_kernel<<<NTOK / TM, 256, smem_bytes>>>(x, cb);

    vq_output_kernel<<<NTOK / 64, 256>>>(x, cb, out, out + NQELEM);
    vq_loss_kernel<<<1, 1>>>(out + NQELEM + NTOK);
}

// round 2
// speedup vs baseline: 1.5251x; 1.5251x over previous
#include <cuda_runtime.h>

// VectorQuantizer: N=16384 tokens (16 x 32 x 32), D=256, K=8192 codes.
// Outputs (float32, concatenated): quantized [16,256,32,32] (4194304),
// indices [16,1024] (16384), vq_loss (1).
//
// R2: packed fp32 FMA (fma.rn.f32x2) doubles the fp32 roofline while keeping
// per-lane IEEE-fused fp32 arithmetic => argmin stays bit-exact vs R1.

#define NTOK   16384
#define KCB    8192
#define DIM    256
#define TM     64
#define TN     256
#define KD     8
#define NQ     4              // K split into quarters for SM load balance
#define KQ     (KCB / NQ)     // 2048
#define NKT    (KQ / TN)      // 8 k-tiles per block
#define NST    (DIM / KD)     // 32 stages per k-tile
#define NQELEM (NTOK * DIM)   // 4194304

typedef unsigned long long ull;

__device__ float  g_sf[NTOK];
__device__ float  g_se[KCB];
__device__ float  g_bd[NQ * NTOK];
__device__ int    g_bi[NQ * NTOK];
__device__ int    g_bestidx[NTOK];
__device__ double g_partial[NTOK / 64];

__device__ __forceinline__ void ffma2(ull& acc, ull a, ull b) {
    asm("fma.rn.f32x2 %0, %1, %2, %0;" : "+l"(acc) : "l"(a), "l"(b));
}
__device__ __forceinline__ ull bcast2(float v) {
    ull r; unsigned u = __float_as_uint(v);
    asm("mov.b64 %0, {%1, %1};" : "=l"(r) : "r"(u));
    return r;
}
__device__ __forceinline__ void unpack2(ull v, float& lo, float& hi) {
    unsigned ulo, uhi;
    asm("mov.b64 {%0, %1}, %2;" : "=r"(ulo), "=r"(uhi) : "l"(v));
    lo = __uint_as_float(ulo); hi = __uint_as_float(uhi);
}

// ---------------------------------------------------------------------------
// sf[t] = sum_c x[b,c,hw]^2, sequential fp32 (anchors the distance grid).
// ---------------------------------------------------------------------------
__global__ void sf_kernel(const float* __restrict__ x) {
    int t = blockIdx.x * blockDim.x + threadIdx.x;
    int b = t >> 10, hw = t & 1023;
    const float* p = x + ((size_t)b << 18) + hw;
    float s = 0.f;
    #pragma unroll 16
    for (int c = 0; c < DIM; c++) {
        float v = p[(size_t)c << 10];
        s = s + v * v;
    }
    g_sf[t] = s;
}

// ---------------------------------------------------------------------------
// se[k] = sum_d cb[k,d]^2. One warp per codebook row.
// ---------------------------------------------------------------------------
__global__ void se_kernel(const float* __restrict__ cb) {
    int k    = blockIdx.x * 8 + (threadIdx.x >> 5);
    int lane = threadIdx.x & 31;
    const float4* row = (const float4*)(cb + (size_t)k * DIM);
    float s = 0.f;
    #pragma unroll
    for (int j = 0; j < 2; j++) {
        float4 v = row[lane + 32 * j];
        s += v.x * v.x + v.y * v.y + v.z * v.z + v.w * v.w;
    }
    #pragma unroll
    for (int o = 16; o; o >>= 1) s += __shfl_xor_sync(0xffffffffu, s, o);
    if (lane == 0) g_se[k] = s;
}

// ---------------------------------------------------------------------------
// Fused distance-GEMM + argmin, f32x2 edition.
// Grid: 1024 blocks = 256 token-tiles x 4 K-quarters. Block: 256 threads
// (8 warps). Warp ty owns token rows ty*8..ty*8+7 (A reads are broadcast);
// lane owns code cols {lane*4..+3} u {128+lane*4..+3}. Per-thread 8x8 tile
// held as 32 f32x2 accumulators (row pairs packed). Accumulation is
// sequential over d=0..255 with fused fp32 FMA per half => bit-identical to
// the scalar R1 kernel.
// ---------------------------------------------------------------------------
__global__ void __launch_bounds__(256, 2)
vq_argmin_kernel(const float* __restrict__ x, const float* __restrict__ cb) {
    extern __shared__ float smem[];
    float* As = smem;               // [DIM][TM]   64 KB
    float* Bs = smem + DIM * TM;    // [2][KD][TN] 16 KB

    const int tid  = threadIdx.x;
    const int lane = tid & 31;
    const int ty   = tid >> 5;                 // warp id 0..7
    const int tile = blockIdx.x & 255;
    const int q    = blockIdx.x >> 8;
    const int m0   = tile * TM;

    // Load A tile (64 tokens share one batch; hw contiguous -> coalesced).
    {
        const int b   = m0 >> 10;
        const int hw0 = m0 & 1023;
        const float* base = x + ((size_t)b << 18) + hw0;
        for (int l = tid; l < DIM * TM; l += 256) {
            int c = l >> 6, i = l & 63;
            As[c * TM + i] = base[((size_t)c << 10) + i];
        }
    }

    float sfm[8];
    #pragma unroll
    for (int r = 0; r < 8; r++) sfm[r] = g_sf[m0 + ty * 8 + r];

    float bestd[8];
    int   besti[8];
    #pragma unroll
    for (int r = 0; r < 8; r++) { bestd[r] = 3.402823466e38f; besti[r] = 0; }

    __syncthreads();

    for (int kt = 0; kt < NKT; kt++) {
        const int k0 = q * KQ + kt * TN;

        ull acc[4][8];
        #pragma unroll
        for (int r2 = 0; r2 < 4; r2++)
            #pragma unroll
            for (int c = 0; c < 8; c++) acc[r2][c] = 0ull;

        const float* crow = cb + (size_t)(k0 + tid) * DIM;

        // Stage 0 load (exposed once per k-tile; tiny vs compute).
        float4 p0 = *(const float4*)(crow + 0);
        float4 p1 = *(const float4*)(crow + 4);
        {
            float* B = Bs;
            B[0 * TN + tid] = p0.x; B[1 * TN + tid] = p0.y;
            B[2 * TN + tid] = p0.z; B[3 * TN + tid] = p0.w;
            B[4 * TN + tid] = p1.x; B[5 * TN + tid] = p1.y;
            B[6 * TN + tid] = p1.z; B[7 * TN + tid] = p1.w;
        }
        __syncthreads();

        for (int s = 0; s < NST; s++) {
            if (s < NST - 1) {                     // prefetch next stage
                p0 = *(const float4*)(crow + (s + 1) * KD);
                p1 = *(const float4*)(crow + (s + 1) * KD + 4);
            }
            const float* B = Bs + (s & 1) * (KD * TN);
            #pragma unroll
            for (int d = 0; d < KD; d++) {
                const ull* pa = (const ull*)&As[(s * KD + d) * TM + ty * 8];
                ull a0 = pa[0], a1 = pa[1], a2 = pa[2], a3 = pa[3];  // broadcast
                float4 b0 = *(const float4*)&B[d * TN + lane * 4];
                float4 b1 = *(const float4*)&B[d * TN + 128 + lane * 4];
                ull bb;
                bb = bcast2(b0.x);
                ffma2(acc[0][0], a0, bb); ffma2(acc[1][0], a1, bb);
                ffma2(acc[2][0], a2, bb); ffma2(acc[3][0], a3, bb);
                bb = bcast2(b0.y);
                ffma2(acc[0][1], a0, bb); ffma2(acc[1][1], a1, bb);
                ffma2(acc[2][1], a2, bb); ffma2(acc[3][1], a3, bb);
                bb = bcast2(b0.z);
                ffma2(acc[0][2], a0, bb); ffma2(acc[1][2], a1, bb);
                ffma2(acc[2][2], a2, bb); ffma2(acc[3][2], a3, bb);
                bb = bcast2(b0.w);
                ffma2(acc[0][3], a0, bb); ffma2(acc[1][3], a1, bb);
                ffma2(acc[2][3], a2, bb); ffma2(acc[3][3], a3, bb);
                bb = bcast2(b1.x);
                ffma2(acc[0][4], a0, bb); ffma2(acc[1][4], a1, bb);
                ffma2(acc[2][4], a2, bb); ffma2(acc[3][4], a3, bb);
                bb = bcast2(b1.y);
                ffma2(acc[0][5], a0, bb); ffma2(acc[1][5], a1, bb);
                ffma2(acc[2][5], a2, bb); ffma2(acc[3][5], a3, bb);
                bb = bcast2(b1.z);
                ffma2(acc[0][6], a0, bb); ffma2(acc[1][6], a1, bb);
                ffma2(acc[2][6], a2, bb); ffma2(acc[3][6], a3, bb);
                bb = bcast2(b1.w);
                ffma2(acc[0][7], a0, bb); ffma2(acc[1][7], a1, bb);
                ffma2(acc[2][7], a2, bb); ffma2(acc[3][7], a3, bb);
            }
            if (s < NST - 1) {                     // store prefetched stage
                float* Bn = Bs + ((s + 1) & 1) * (KD * TN);
                Bn[0 * TN + tid] = p0.x; Bn[1 * TN + tid] = p0.y;
                Bn[2 * TN + tid] = p0.z; Bn[3 * TN + tid] = p0.w;
                Bn[4 * TN + tid] = p1.x; Bn[5 * TN + tid] = p1.y;
                Bn[6 * TN + tid] = p1.z; Bn[7 * TN + tid] = p1.w;
            }
            __syncthreads();
        }

        // Epilogue: distances + running argmin (k ascending within the scan;
        // strict < keeps the first index).
        float4 se0 = *(const float4*)&g_se[k0 + lane * 4];
        float4 se1 = *(const float4*)&g_se[k0 + 128 + lane * 4];
        const float sec[8] = {se0.x, se0.y, se0.z, se0.w,
                              se1.x, se1.y, se1.z, se1.w};
        #pragma unroll
        for (int c = 0; c < 8; c++) {
            const int kidx = k0 + (c < 4 ? lane * 4 + c : 128 + lane * 4 + (c - 4));
            #pragma unroll
            for (int r2 = 0; r2 < 4; r2++) {
                float alo, ahi;
                unpack2(acc[r2][c], alo, ahi);
                const int r = 2 * r2;
                float dl = __fmaf_rn(-2.0f, alo, sfm[r]) + sec[c];
                if (dl < bestd[r]) { bestd[r] = dl; besti[r] = kidx; }
                float dh = __fmaf_rn(-2.0f, ahi, sfm[r + 1]) + sec[c];
                if (dh < bestd[r + 1]) { bestd[r + 1] = dh; besti[r + 1] = kidx; }
            }
        }
    }

    // Warp-level argmin reduce across the 32 lanes (lex min on (dist, idx)
    // == first-index tie break; order-independent => deterministic).
    #pragma unroll
    for (int r = 0; r < 8; r++) {
        float bd = bestd[r];
        int   bi = besti[r];
        #pragma unroll
        for (int off = 16; off; off >>= 1) {
            float od = __shfl_xor_sync(0xffffffffu, bd, off);
            int   oi = __shfl_xor_sync(0xffffffffu, bi, off);
            if (od < bd || (od == bd && oi < bi)) { bd = od; bi = oi; }
        }
        if (lane == 0) {
            g_bd[q * NTOK + m0 + ty * 8 + r] = bd;
            g_bi[q * NTOK + m0 + ty * 8 + r] = bi;
        }
    }
}

// ---------------------------------------------------------------------------
// Combine the 4 K-quarter candidates per token (lex min on (dist, idx)).
// ---------------------------------------------------------------------------
__global__ void vq_combine_kernel() {
    int t = blockIdx.x * 256 + threadIdx.x;
    float bd = g_bd[t];
    int   bi = g_bi[t];
    #pragma unroll
    for (int qq = 1; qq < NQ; qq++) {
        float d2 = g_bd[qq * NTOK + t];
        int   i2 = g_bi[qq * NTOK + t];
        if (d2 < bd || (d2 == bd && i2 < bi)) { bd = d2; bi = i2; }
    }
    g_bestidx[t] = bi;
}

// ---------------------------------------------------------------------------
// Gather + straight-through output + indices + loss partials.
// ---------------------------------------------------------------------------
__global__ void __launch_bounds__(256) vq_output_kernel(const float* __restrict__ x,
                                                        const float* __restrict__ cb,
                                                        float* __restrict__ out,
                                                        float* __restrict__ idx_out) {
    __shared__ double sred[256];
    const int tid = threadIdx.x;
    const int m0  = blockIdx.x * 64;
    const int t   = m0 + (tid & 63);
    const int cg  = tid >> 6;
    const int b = t >> 10, hw = t & 1023;
    const int idx = g_bestidx[t];
    const float* xp  = x  + ((size_t)b << 18) + hw;
    const float* cbp = cb + (size_t)idx * DIM;
    float* op = out + ((size_t)b << 18) + hw;
    double ls = 0.0;
    for (int c = cg * 64; c < cg * 64 + 64; c++) {
        float xv = xp[(size_t)c << 10];
        float qv = cbp[c];
        float d  = qv - xv;
        op[(size_t)c << 10] = xv + d;
        ls += (double)(d * d);
    }
    if (cg == 0) idx_out[t] = (float)idx;
    sred[tid] = ls;
    __syncthreads();
    for (int o = 128; o; o >>= 1) {
        if (tid < o) sred[tid] += sred[tid + o];
        __syncthreads();
    }
    if (tid == 0) g_partial[blockIdx.x] = sred[0];
}

__global__ void vq_loss_kernel(float* __restrict__ loss_out) {
    double s = 0.0;
    for (int i = 0; i < NTOK / 64; i++) s += g_partial[i];
    float m = (float)(s / (double)NQELEM);
    loss_out[0] = m + 0.25f * m;
}

// ---------------------------------------------------------------------------
extern "C" void kernel_launch(void* const* d_in, const int* in_sizes, int n_in,
                              void* d_out, int out_size) {
    const float* x  = (const float*)d_in[0];
    const float* cb = (const float*)d_in[1];
    if (n_in >= 2 && in_sizes[0] == KCB * DIM && in_sizes[1] == NQELEM) {
        const float* tmp = x; x = cb; cb = tmp;   // defensive: swapped order
    }
    float* out = (float*)d_out;

    sf_kernel<<<NTOK / 256, 256>>>(x);
    se_kernel<<<KCB / 8, 256>>>(cb);

    const size_t smem_bytes = (size_t)(DIM * TM + 2 * KD * TN) * sizeof(float); // 81920
    cudaFuncSetAttribute(vq_argmin_kernel,
                         cudaFuncAttributeMaxDynamicSharedMemorySize,
                         (int)smem_bytes);
    vq_argmin_kernel<<<256 * NQ, 256, smem_bytes>>>(x, cb);

    vq_combine_kernel<<<NTOK / 256, 256>>>();
    vq_output_kernel<<<NTOK / 64, 256>>>(x, cb, out, out + NQELEM);
    vq_loss_kernel<<<1, 1>>>(out + NQELEM + NTOK);
}